// round 11
// baseline (speedup 1.0000x reference)
#include <cuda_runtime.h>
#include <cuda_fp16.h>

#define BB 128
#define TT 512
#define CC 128

#define EBIAS 2.5f            // E' = exp(trans - EBIAS)
#define GROW  3.85f           // growth recentering folded into ef scale
#define KSCALE 0.0212797f     // exp(-GROW)
#define MSTEP 6.35f           // EBIAS + GROW added to m each step

__device__ float g_partial[BB];

__device__ __forceinline__ float block_reduce_sum_128(float v, float* sh4) {
    #pragma unroll
    for (int o = 16; o > 0; o >>= 1)
        v += __shfl_xor_sync(0xffffffffu, v, o);
    int w = threadIdx.x >> 5;
    if ((threadIdx.x & 31) == 0) sh4[w] = v;
    __syncthreads();
    float r = (sh4[0] + sh4[1]) + (sh4[2] + sh4[3]);
    __syncthreads();
    return r;
}

__global__ __launch_bounds__(128, 1)
void crf_forward_kernel(const float* __restrict__ feats,
                        const int*   __restrict__ mask,
                        const int*   __restrict__ tags,
                        const float* __restrict__ trans)
{
    const int b = blockIdx.x;
    const int j = threadIdx.x;           // owns class column j

    __shared__ __align__(16) __half p_s[2][CC];
    __shared__ float sh4[4];

    // ---- sequence length (contiguous prefix mask) ----
    const int* mrow = mask + b * TT;
    int cnt = 0;
    #pragma unroll
    for (int t = 0; t < 4; t++) cnt += mrow[j + t * 128];
    const int L = (int)block_reduce_sum_128((float)cnt, sh4);

    // ---- E column in fp16, two complementarily-rounded copies ----
    __half2 E2a[64], E2b[64];
    #pragma unroll
    for (int ii = 0; ii < 64; ii++) {
        float lo = __expf(trans[(2 * ii + 0) * CC + j] - EBIAS);  // exp(-1e5)->0
        float hi = __expf(trans[(2 * ii + 1) * CC + j] - EBIAS);
        __half hlo = __float2half_rn(lo), hhi = __float2half_rn(hi);
        E2a[ii] = __halves2half2(hlo, hhi);
        __half blo = __float2half_rn(2.0f * lo - __half2float(hlo));
        __half bhi = __float2half_rn(2.0f * hi - __half2float(hhi));
        E2b[ii] = __halves2half2(blo, bhi);
    }

    // ---- init: p = one-hot(START) ----
    p_s[0][j] = __float2half_rn((j == CC - 2) ? 1.0f : 0.0f);
    __syncthreads();

    const float* fb = feats + (size_t)b * TT * CC + j;
    float m   = 0.0f;
    float ef0 = __expf(fb[0]);                        // L >= 1 always
    float ef1 = (L > 1) ? __expf(fb[CC]) : 1.0f;
    int cur = 0;

    // ---- forward scan: one barrier per step, all-fp16 tail ----
    for (int t = 0; t < L; t++) {
        // step-top (overlaps matvec): scale from prev p[0], fold ef + recenter
        float c = (t == 0) ? 1.0f : __half2float(p_s[cur][0]);
        float ef_eff = (ef0 * KSCALE) * __fdividef(1.0f, c);
        __half efh = __float2half_rn(ef_eff);

        float ef2 = (t + 2 < L) ? __expf(fb[(size_t)(t + 2) * CC]) : 1.0f;

        // matvec: 64 HFMA2, 8 chains of depth 8
        const __half2* Ecol = (t & 1) ? E2b : E2a;
        const uint4* pv = (const uint4*)p_s[cur];
        __half2 acc[8];
        #pragma unroll
        for (int k = 0; k < 8; k++) acc[k] = __floats2half2_rn(0.f, 0.f);
        #pragma unroll
        for (int ii = 0; ii < 16; ii++) {
            uint4 q = pv[ii];
            __half2 q0 = *reinterpret_cast<__half2*>(&q.x);
            __half2 q1 = *reinterpret_cast<__half2*>(&q.y);
            __half2 q2 = *reinterpret_cast<__half2*>(&q.z);
            __half2 q3 = *reinterpret_cast<__half2*>(&q.w);
            acc[(4 * ii + 0) & 7] = __hfma2(q0, Ecol[4 * ii + 0], acc[(4 * ii + 0) & 7]);
            acc[(4 * ii + 1) & 7] = __hfma2(q1, Ecol[4 * ii + 1], acc[(4 * ii + 1) & 7]);
            acc[(4 * ii + 2) & 7] = __hfma2(q2, Ecol[4 * ii + 2], acc[(4 * ii + 2) & 7]);
            acc[(4 * ii + 3) & 7] = __hfma2(q3, Ecol[4 * ii + 3], acc[(4 * ii + 3) & 7]);
        }

        // fp16 tree: 7 HADD2 + cross-half HADD + HMUL, then STS.16 — no F2F
        __half2 t4a = __hadd2(acc[0], acc[1]);
        __half2 t4b = __hadd2(acc[2], acc[3]);
        __half2 t4c = __hadd2(acc[4], acc[5]);
        __half2 t4d = __hadd2(acc[6], acc[7]);
        __half2 s2  = __hadd2(__hadd2(t4a, t4b), __hadd2(t4c, t4d));
        __half  sh  = __hadd(__low2half(s2), __high2half(s2));
        p_s[cur ^ 1][j] = __hmul(sh, efh);

        m += MSTEP + __logf(c);          // off critical path

        ef0 = ef1; ef1 = ef2;
        cur ^= 1;
        __syncthreads();
    }

    // ---- logZ = m + log( sum_j p[j] * exp(trans[j][STOP]) ) ----
    float contrib = __half2float(p_s[cur][j]) * __expf(trans[j * CC + (CC - 1)]);
    float tot = block_reduce_sum_128(contrib, sh4);
    float logZ = m + __logf(tot);

    // ---- gold path score (fp32 exact) ----
    const int* tg = tags + b * TT;
    const float* fbase = feats + (size_t)b * TT * CC;
    float sc = 0.0f;
    for (int tt = j; tt < L; tt += 128)
        sc += fbase[(size_t)tt * CC + tg[tt]];
    for (int k = j; k <= L; k += 128) {
        int prev = (k == 0) ? (CC - 2) : tg[k - 1];
        int curt = (k == L) ? (CC - 1) : tg[k];
        sc += trans[prev * CC + curt];
    }
    float tots = block_reduce_sum_128(sc, sh4);

    if (j == 0) g_partial[b] = logZ - tots;
}

__global__ void crf_finalize_kernel(float* __restrict__ out)
{
    __shared__ float s[BB];
    int tid = threadIdx.x;
    s[tid] = g_partial[tid];
    __syncthreads();
    #pragma unroll
    for (int off = 64; off > 0; off >>= 1) {
        if (tid < off) s[tid] += s[tid + off];
        __syncthreads();
    }
    if (tid == 0) out[0] = s[0] / (float)BB;
}

extern "C" void kernel_launch(void* const* d_in, const int* in_sizes, int n_in,
                              void* d_out, int out_size)
{
    const float* feats = (const float*)d_in[0];
    const int*   mask  = (const int*)  d_in[1];
    const int*   tags  = (const int*)  d_in[2];
    const float* trans = (const float*)d_in[3];
    float* out = (float*)d_out;

    crf_forward_kernel<<<BB, 128>>>(feats, mask, tags, trans);
    crf_finalize_kernel<<<1, BB>>>(out);
}

// round 12
// speedup vs baseline: 1.3406x; 1.3406x over previous
#include <cuda_runtime.h>
#include <cuda_fp16.h>

#define BB 128
#define TT 512
#define CC 128

#define EBIAS 2.5f            // E' = exp(trans - EBIAS)
#define GROW  3.85f           // growth recentering folded into ef scale
#define KSCALE 0.0212797f     // exp(-GROW)
#define MSTEP 6.35f           // EBIAS + GROW added to m each step

__device__ float g_partial[BB];

__device__ __forceinline__ float block_reduce_sum_128(float v, float* sh4) {
    #pragma unroll
    for (int o = 16; o > 0; o >>= 1)
        v += __shfl_xor_sync(0xffffffffu, v, o);
    int w = threadIdx.x >> 5;
    if ((threadIdx.x & 31) == 0) sh4[w] = v;
    __syncthreads();
    float r = (sh4[0] + sh4[1]) + (sh4[2] + sh4[3]);
    __syncthreads();
    return r;
}

// One forward step. ECOL must be a register-array NAME (no indirection, so the
// array stays register-resident). CUR is the compile-time ping-pong index.
#define CRF_STEP(ECOL, CUR, t)                                                   \
    {                                                                            \
        /* scale factor from prev p[0] (broadcast LDS, overlaps matvec) */      \
        float c = ((t) == 0) ? 1.0f : __half2float(p_s[CUR][0]);                 \
        float ef_eff = (ef0 * KSCALE) * __fdividef(1.0f, c);                     \
        __half efh = __float2half_rn(ef_eff);                                    \
        float ef2 = ((t) + 2 < L) ? __expf(fb[(size_t)((t) + 2) * CC]) : 1.0f;   \
        const uint4* pv = (const uint4*)p_s[CUR];                                \
        __half2 acc0 = __floats2half2_rn(0.f, 0.f), acc1 = acc0, acc2 = acc0,    \
                acc3 = acc0, acc4 = acc0, acc5 = acc0, acc6 = acc0, acc7 = acc0; \
        _Pragma("unroll")                                                        \
        for (int ii = 0; ii < 16; ii++) {                                        \
            uint4 q = pv[ii];                                                    \
            __half2 q0 = *reinterpret_cast<__half2*>(&q.x);                      \
            __half2 q1 = *reinterpret_cast<__half2*>(&q.y);                      \
            __half2 q2 = *reinterpret_cast<__half2*>(&q.z);                      \
            __half2 q3 = *reinterpret_cast<__half2*>(&q.w);                      \
            if ((ii & 1) == 0) {                                                 \
                acc0 = __hfma2(q0, ECOL[4 * ii + 0], acc0);                      \
                acc1 = __hfma2(q1, ECOL[4 * ii + 1], acc1);                      \
                acc2 = __hfma2(q2, ECOL[4 * ii + 2], acc2);                      \
                acc3 = __hfma2(q3, ECOL[4 * ii + 3], acc3);                      \
            } else {                                                             \
                acc4 = __hfma2(q0, ECOL[4 * ii + 0], acc4);                      \
                acc5 = __hfma2(q1, ECOL[4 * ii + 1], acc5);                      \
                acc6 = __hfma2(q2, ECOL[4 * ii + 2], acc6);                      \
                acc7 = __hfma2(q3, ECOL[4 * ii + 3], acc7);                      \
            }                                                                    \
        }                                                                        \
        __half2 t4a = __hadd2(acc0, acc1);                                       \
        __half2 t4b = __hadd2(acc2, acc3);                                       \
        __half2 t4c = __hadd2(acc4, acc5);                                       \
        __half2 t4d = __hadd2(acc6, acc7);                                       \
        __half2 s2  = __hadd2(__hadd2(t4a, t4b), __hadd2(t4c, t4d));             \
        __half  shh = __hadd(__low2half(s2), __high2half(s2));                   \
        p_s[(CUR) ^ 1][j] = __hmul(shh, efh);                                    \
        m += MSTEP + __logf(c);                                                  \
        ef0 = ef1; ef1 = ef2;                                                    \
        __syncthreads();                                                         \
    }

__global__ __launch_bounds__(128, 1)
void crf_forward_kernel(const float* __restrict__ feats,
                        const int*   __restrict__ mask,
                        const int*   __restrict__ tags,
                        const float* __restrict__ trans)
{
    const int b = blockIdx.x;
    const int j = threadIdx.x;           // owns class column j

    __shared__ __align__(16) __half p_s[2][CC];
    __shared__ float sh4[4];

    // ---- sequence length (contiguous prefix mask) ----
    const int* mrow = mask + b * TT;
    int cnt = 0;
    #pragma unroll
    for (int t = 0; t < 4; t++) cnt += mrow[j + t * 128];
    const int L = (int)block_reduce_sum_128((float)cnt, sh4);

    // ---- E column in fp16, two complementarily-rounded copies (bias cancel) ----
    __half2 E2a[64], E2b[64];
    #pragma unroll
    for (int ii = 0; ii < 64; ii++) {
        float lo = __expf(trans[(2 * ii + 0) * CC + j] - EBIAS);  // exp(-1e5)->0
        float hi = __expf(trans[(2 * ii + 1) * CC + j] - EBIAS);
        __half hlo = __float2half_rn(lo), hhi = __float2half_rn(hi);
        E2a[ii] = __halves2half2(hlo, hhi);
        __half blo = __float2half_rn(2.0f * lo - __half2float(hlo));
        __half bhi = __float2half_rn(2.0f * hi - __half2float(hhi));
        E2b[ii] = __halves2half2(blo, bhi);
    }

    // ---- init: p = one-hot(START) ----
    p_s[0][j] = __float2half_rn((j == CC - 2) ? 1.0f : 0.0f);
    __syncthreads();

    const float* fb = feats + (size_t)b * TT * CC + j;
    float m   = 0.0f;
    float ef0 = __expf(fb[0]);                        // L >= 1 always
    float ef1 = (L > 1) ? __expf(fb[CC]) : 1.0f;

    // ---- forward scan: 2 steps per trip, ping-pong fully unrolled ----
    int t = 0;
    int nPairs = L >> 1;
    for (int p = 0; p < nPairs; p++) {
        CRF_STEP(E2a, 0, t); t++;
        CRF_STEP(E2b, 1, t); t++;
    }
    int cur = 0;
    if (t < L) {                 // odd tail step
        CRF_STEP(E2a, 0, t); t++;
        cur = 1;
    }

    // ---- logZ = m + log( sum_j p[j] * exp(trans[j][STOP]) ) ----
    float contrib = __half2float(p_s[cur][j]) * __expf(trans[j * CC + (CC - 1)]);
    float tot = block_reduce_sum_128(contrib, sh4);
    float logZ = m + __logf(tot);

    // ---- gold path score (fp32 exact) ----
    const int* tg = tags + b * TT;
    const float* fbase = feats + (size_t)b * TT * CC;
    float sc = 0.0f;
    for (int tt = j; tt < L; tt += 128)
        sc += fbase[(size_t)tt * CC + tg[tt]];
    for (int k = j; k <= L; k += 128) {
        int prev = (k == 0) ? (CC - 2) : tg[k - 1];
        int curt = (k == L) ? (CC - 1) : tg[k];
        sc += trans[prev * CC + curt];
    }
    float tots = block_reduce_sum_128(sc, sh4);

    if (j == 0) g_partial[b] = logZ - tots;
}

__global__ void crf_finalize_kernel(float* __restrict__ out)
{
    __shared__ float s[BB];
    int tid = threadIdx.x;
    s[tid] = g_partial[tid];
    __syncthreads();
    #pragma unroll
    for (int off = 64; off > 0; off >>= 1) {
        if (tid < off) s[tid] += s[tid + off];
        __syncthreads();
    }
    if (tid == 0) out[0] = s[0] / (float)BB;
}

extern "C" void kernel_launch(void* const* d_in, const int* in_sizes, int n_in,
                              void* d_out, int out_size)
{
    const float* feats = (const float*)d_in[0];
    const int*   mask  = (const int*)  d_in[1];
    const int*   tags  = (const int*)  d_in[2];
    const float* trans = (const float*)d_in[3];
    float* out = (float*)d_out;

    crf_forward_kernel<<<BB, 128>>>(feats, mask, tags, trans);
    crf_finalize_kernel<<<1, BB>>>(out);
}

// round 13
// speedup vs baseline: 1.5331x; 1.1436x over previous
#include <cuda_runtime.h>
#include <cuda_fp16.h>

#define BB 128
#define TT 512
#define CC 128

#define EBIAS 2.5f            // E' = exp(trans - EBIAS)
#define GROW  3.85f           // growth recentering folded into ef scale
#define KSCALE 0.0212797f     // exp(-GROW)
#define MSTEP 6.35f           // EBIAS + GROW added to m each step

__device__ float g_partial[BB];

__device__ __forceinline__ float block_reduce_sum_256(float v, float* sh8) {
    #pragma unroll
    for (int o = 16; o > 0; o >>= 1)
        v += __shfl_xor_sync(0xffffffffu, v, o);
    int w = threadIdx.x >> 5;
    if ((threadIdx.x & 31) == 0) sh8[w] = v;
    __syncthreads();
    float r = ((sh8[0] + sh8[1]) + (sh8[2] + sh8[3]))
            + ((sh8[4] + sh8[5]) + (sh8[6] + sh8[7]));
    __syncthreads();
    return r;
}

// One forward step. ECOL must be a register-array NAME (stays register-resident).
// Thread (j, h): half-matvec over i in [h*64, h*64+64), combine via shfl_xor(16)
// (both half-lanes of column j live in the same warp). One __syncthreads total.
#define CRF_STEP(ECOL, CUR, t)                                                   \
    {                                                                            \
        float c = ((t) == 0) ? 1.0f : __half2float(p_s[CUR][0]);                 \
        float ef_eff = (ef0 * KSCALE) * __fdividef(1.0f, c);                     \
        float ef2 = ((t) + 2 < L) ? __expf(fb[(size_t)((t) + 2) * CC]) : 1.0f;   \
        const uint4* pv = (const uint4*)(p_s[CUR] + (h << 6));                   \
        __half2 acc0 = __floats2half2_rn(0.f, 0.f), acc1 = acc0, acc2 = acc0,    \
                acc3 = acc0, acc4 = acc0, acc5 = acc0, acc6 = acc0, acc7 = acc0; \
        _Pragma("unroll")                                                        \
        for (int ii = 0; ii < 8; ii++) {                                         \
            uint4 q = pv[ii];                                                    \
            __half2 q0 = *reinterpret_cast<__half2*>(&q.x);                      \
            __half2 q1 = *reinterpret_cast<__half2*>(&q.y);                      \
            __half2 q2 = *reinterpret_cast<__half2*>(&q.z);                      \
            __half2 q3 = *reinterpret_cast<__half2*>(&q.w);                      \
            if ((ii & 1) == 0) {                                                 \
                acc0 = __hfma2(q0, ECOL[4 * ii + 0], acc0);                      \
                acc1 = __hfma2(q1, ECOL[4 * ii + 1], acc1);                      \
                acc2 = __hfma2(q2, ECOL[4 * ii + 2], acc2);                      \
                acc3 = __hfma2(q3, ECOL[4 * ii + 3], acc3);                      \
            } else {                                                             \
                acc4 = __hfma2(q0, ECOL[4 * ii + 0], acc4);                      \
                acc5 = __hfma2(q1, ECOL[4 * ii + 1], acc5);                      \
                acc6 = __hfma2(q2, ECOL[4 * ii + 2], acc6);                      \
                acc7 = __hfma2(q3, ECOL[4 * ii + 3], acc7);                      \
            }                                                                    \
        }                                                                        \
        __half2 t4a = __hadd2(acc0, acc1);                                       \
        __half2 t4b = __hadd2(acc2, acc3);                                       \
        __half2 t4c = __hadd2(acc4, acc5);                                       \
        __half2 t4d = __hadd2(acc6, acc7);                                       \
        __half2 s2  = __hadd2(__hadd2(t4a, t4b), __hadd2(t4c, t4d));             \
        float smine = __half2float(__hadd(__low2half(s2), __high2half(s2)));     \
        float sfull = smine + __shfl_xor_sync(0xffffffffu, smine, 16);           \
        if (h == 0) p_s[(CUR) ^ 1][j] = __float2half_rn(sfull * ef_eff);         \
        m += MSTEP + __logf(c);                                                  \
        ef0 = ef1; ef1 = ef2;                                                    \
        __syncthreads();                                                         \
    }

__global__ __launch_bounds__(256, 1)
void crf_forward_kernel(const float* __restrict__ feats,
                        const int*   __restrict__ mask,
                        const int*   __restrict__ tags,
                        const float* __restrict__ trans)
{
    const int b   = blockIdx.x;
    const int tid = threadIdx.x;
    const int w   = tid >> 5;
    const int l   = tid & 31;
    const int j   = (w << 4) | (l & 15);   // class column owned
    const int h   = l >> 4;                // i-half (same warp as sibling lane)

    __shared__ __align__(16) __half p_s[2][CC];
    __shared__ float sh8[8];

    // ---- sequence length (contiguous prefix mask) ----
    const int* mrow = mask + b * TT;
    int cnt = mrow[tid] + mrow[tid + 256];
    const int L = (int)block_reduce_sum_256((float)cnt, sh8);

    // ---- E half-column in fp16, two complementarily-rounded copies ----
    __half2 E2a[32], E2b[32];
    #pragma unroll
    for (int ii = 0; ii < 32; ii++) {
        int i0 = (h << 6) + 2 * ii;
        float lo = __expf(trans[(i0 + 0) * CC + j] - EBIAS);  // exp(-1e5)->0
        float hi = __expf(trans[(i0 + 1) * CC + j] - EBIAS);
        __half hlo = __float2half_rn(lo), hhi = __float2half_rn(hi);
        E2a[ii] = __halves2half2(hlo, hhi);
        __half blo = __float2half_rn(2.0f * lo - __half2float(hlo));
        __half bhi = __float2half_rn(2.0f * hi - __half2float(hhi));
        E2b[ii] = __halves2half2(blo, bhi);
    }

    // ---- init: p = one-hot(START) ----
    if (h == 0) p_s[0][j] = __float2half_rn((j == CC - 2) ? 1.0f : 0.0f);
    __syncthreads();

    const float* fb = feats + (size_t)b * TT * CC + j;
    float m   = 0.0f;
    float ef0 = __expf(fb[0]);                        // L >= 1 always
    float ef1 = (L > 1) ? __expf(fb[CC]) : 1.0f;

    // ---- forward scan: 2 steps per trip, ping-pong unrolled ----
    int t = 0;
    int nPairs = L >> 1;
    for (int p = 0; p < nPairs; p++) {
        CRF_STEP(E2a, 0, t); t++;
        CRF_STEP(E2b, 1, t); t++;
    }
    int cur = 0;
    if (t < L) {                 // odd tail step
        CRF_STEP(E2a, 0, t); t++;
        cur = 1;
    }

    // ---- logZ = m + log( sum_j p[j] * exp(trans[j][STOP]) ) ----
    float contrib = (h == 0)
        ? __half2float(p_s[cur][j]) * __expf(trans[j * CC + (CC - 1)]) : 0.0f;
    float tot = block_reduce_sum_256(contrib, sh8);
    float logZ = m + __logf(tot);

    // ---- gold path score (fp32 exact) ----
    const int* tg = tags + b * TT;
    const float* fbase = feats + (size_t)b * TT * CC;
    float sc = 0.0f;
    for (int tt = tid; tt < L; tt += 256)
        sc += fbase[(size_t)tt * CC + tg[tt]];
    for (int k = tid; k <= L; k += 256) {
        int prev = (k == 0) ? (CC - 2) : tg[k - 1];
        int curt = (k == L) ? (CC - 1) : tg[k];
        sc += trans[prev * CC + curt];
    }
    float tots = block_reduce_sum_256(sc, sh8);

    if (tid == 0) g_partial[b] = logZ - tots;
}

__global__ void crf_finalize_kernel(float* __restrict__ out)
{
    __shared__ float s[BB];
    int tid = threadIdx.x;
    s[tid] = g_partial[tid];
    __syncthreads();
    #pragma unroll
    for (int off = 64; off > 0; off >>= 1) {
        if (tid < off) s[tid] += s[tid + off];
        __syncthreads();
    }
    if (tid == 0) out[0] = s[0] / (float)BB;
}

extern "C" void kernel_launch(void* const* d_in, const int* in_sizes, int n_in,
                              void* d_out, int out_size)
{
    const float* feats = (const float*)d_in[0];
    const int*   mask  = (const int*)  d_in[1];
    const int*   tags  = (const int*)  d_in[2];
    const float* trans = (const float*)d_in[3];
    float* out = (float*)d_out;

    crf_forward_kernel<<<BB, 256>>>(feats, mask, tags, trans);
    crf_finalize_kernel<<<1, BB>>>(out);
}